// round 3
// baseline (speedup 1.0000x reference)
#include <cuda_runtime.h>
#include <math.h>

// ---------------- problem constants ----------------
#define NMAX 50000
#define EMAX 800000
#define CH   128
#define LOUT 64

// ---------------- device scratch ----------------
__device__ float g_deg[NMAX];
__device__ float g_dis[NMAX];
__device__ float g_selfnorm[NMAX];
__device__ int   g_count[NMAX];
__device__ int   g_rowstart[NMAX + 1];
__device__ int   g_cursor[NMAX];
__device__ int   g_csr_src[EMAX];
__device__ float g_csr_nm[EMAX];
__device__ float g_tmp[(size_t)NMAX * CH];   // GEMM output
__device__ float g_agg[(size_t)NMAX * CH];   // aggregation output
__device__ float g_bnsum[CH];
__device__ float g_bnsq[CH];
__device__ float g_scale[CH];
__device__ float g_shift[CH];
__device__ int   g_is64;

// ---------------- helpers ----------------
__device__ __forceinline__ int fetch_idx(const void* p, long long i, int is64) {
    if (is64) return (int)((const long long*)p)[i];
    return ((const int*)p)[i];
}

// init: deg=1 (self loop), count=0, zero bn accumulators, detect idx width
__global__ void k_init(const void* ei, int N) {
    int i = blockIdx.x * blockDim.x + threadIdx.x;
    if (i < N) { g_deg[i] = 1.0f; g_count[i] = 0; }
    if (blockIdx.x == 0) {
        if (threadIdx.x < CH) { g_bnsum[threadIdx.x] = 0.f; g_bnsq[threadIdx.x] = 0.f; }
        if (threadIdx.x == 0) {
            const int* w = (const int*)ei;
            int z = 1;
            #pragma unroll
            for (int q = 1; q <= 9; q += 2) if (w[q] != 0) z = 0;
            g_is64 = z;
        }
    }
}

__global__ void k_deg(const void* ei, const float* __restrict__ ew, int E) {
    int e = blockIdx.x * blockDim.x + threadIdx.x;
    if (e >= E) return;
    int is64 = g_is64;
    int d = fetch_idx(ei, (long long)E + e, is64);
    atomicAdd(&g_deg[d], ew[e]);
    atomicAdd(&g_count[d], 1);
}

// single block: compute dis/selfnorm, exclusive scan count -> rowstart/cursor
__global__ void k_scan_dis(int N) {
    __shared__ int ssum[1024];
    int t = threadIdx.x;
    int chunk = (N + 1023) / 1024;
    int lo = t * chunk;
    int hi = min(lo + chunk, N);
    int s = 0;
    for (int i = lo; i < hi; i++) {
        s += g_count[i];
        float d = rsqrtf(g_deg[i]);
        g_dis[i] = d;
        g_selfnorm[i] = d * d;
    }
    ssum[t] = s;
    __syncthreads();
    for (int off = 1; off < 1024; off <<= 1) {
        int v = (t >= off) ? ssum[t - off] : 0;
        __syncthreads();
        ssum[t] += v;
        __syncthreads();
    }
    int base = (t == 0) ? 0 : ssum[t - 1];
    for (int i = lo; i < hi; i++) {
        g_rowstart[i] = base;
        g_cursor[i]   = base;
        base += g_count[i];
    }
    if (t == 1023) g_rowstart[N] = ssum[1023];
}

__global__ void k_fill(const void* ei, const float* __restrict__ ew, int E) {
    int e = blockIdx.x * blockDim.x + threadIdx.x;
    if (e >= E) return;
    int is64 = g_is64;
    int s = fetch_idx(ei, e, is64);
    int d = fetch_idx(ei, (long long)E + e, is64);
    float nm = g_dis[s] * ew[e] * g_dis[d];
    int pos = atomicAdd(&g_cursor[d], 1);
    g_csr_src[pos] = s;
    g_csr_nm[pos]  = nm;
}

// ---------------- SGEMM: g_tmp = bn_relu?(A)[N,128] @ W[128,COUT] ----------------
template<int COUT, bool BN>
__global__ __launch_bounds__(256) void k_gemm(const float* __restrict__ A,
                                              const float* __restrict__ W, int N) {
    constexpr int BM = 128, BK = 32, TN = COUT / 16;
    __shared__ float As[BK][BM + 4];
    __shared__ float Bs[BK][COUT];
    __shared__ float s_scale[128];
    __shared__ float s_shift[128];
    int tid = threadIdx.x;
    int brow = blockIdx.x * BM;
    int ty = tid >> 4, tx = tid & 15;

    if (BN) {
        if (tid < 128) { s_scale[tid] = g_scale[tid]; s_shift[tid] = g_shift[tid]; }
        __syncthreads();
    }

    float acc[8][TN];
    #pragma unroll
    for (int i = 0; i < 8; i++)
        #pragma unroll
        for (int j = 0; j < TN; j++) acc[i][j] = 0.f;

    for (int k0 = 0; k0 < 128; k0 += BK) {
        // A tile: 128 rows x 32 k, transposed into As[k][row]
        #pragma unroll
        for (int q = 0; q < 4; q++) {
            int f = tid + q * 256;         // 0..1023 float4s
            int row = f >> 3, kq = f & 7;
            int gr = brow + row;
            float4 v = make_float4(0.f, 0.f, 0.f, 0.f);
            if (gr < N) v = *(const float4*)&A[(size_t)gr * 128 + k0 + kq * 4];
            if (BN) {
                int c = k0 + kq * 4;
                v.x = fmaxf(fmaf(v.x, s_scale[c + 0], s_shift[c + 0]), 0.f);
                v.y = fmaxf(fmaf(v.y, s_scale[c + 1], s_shift[c + 1]), 0.f);
                v.z = fmaxf(fmaf(v.z, s_scale[c + 2], s_shift[c + 2]), 0.f);
                v.w = fmaxf(fmaf(v.w, s_scale[c + 3], s_shift[c + 3]), 0.f);
            }
            As[kq * 4 + 0][row] = v.x;
            As[kq * 4 + 1][row] = v.y;
            As[kq * 4 + 2][row] = v.z;
            As[kq * 4 + 3][row] = v.w;
        }
        // B tile: 32 x COUT
        constexpr int BF4 = BK * COUT / 4;
        #pragma unroll
        for (int f = tid; f < BF4; f += 256) {
            int row = f / (COUT / 4), cq = f % (COUT / 4);
            *(float4*)&Bs[row][cq * 4] = *(const float4*)&W[(size_t)(k0 + row) * COUT + cq * 4];
        }
        __syncthreads();
        #pragma unroll
        for (int kk = 0; kk < BK; kk++) {
            float a[8], b[TN];
            #pragma unroll
            for (int i = 0; i < 2; i++) {
                float4 av = *(const float4*)&As[kk][ty * 8 + i * 4];
                a[i * 4 + 0] = av.x; a[i * 4 + 1] = av.y;
                a[i * 4 + 2] = av.z; a[i * 4 + 3] = av.w;
            }
            #pragma unroll
            for (int j = 0; j < TN / 4; j++) {
                float4 bv = *(const float4*)&Bs[kk][tx * TN + j * 4];
                b[j * 4 + 0] = bv.x; b[j * 4 + 1] = bv.y;
                b[j * 4 + 2] = bv.z; b[j * 4 + 3] = bv.w;
            }
            #pragma unroll
            for (int i = 0; i < 8; i++)
                #pragma unroll
                for (int j = 0; j < TN; j++)
                    acc[i][j] = fmaf(a[i], b[j], acc[i][j]);
        }
        __syncthreads();
    }
    #pragma unroll
    for (int i = 0; i < 8; i++) {
        int r = brow + ty * 8 + i;
        if (r < N) {
            #pragma unroll
            for (int j = 0; j < TN / 4; j++)
                *(float4*)&g_tmp[(size_t)r * COUT + tx * TN + j * 4] =
                    make_float4(acc[i][j * 4], acc[i][j * 4 + 1], acc[i][j * 4 + 2], acc[i][j * 4 + 3]);
        }
    }
}

// ---------------- aggregation (warp/node) + fused BN stats ----------------
template<int COUT>
__global__ __launch_bounds__(512) void k_agg(const float* __restrict__ bias, int N) {
    constexpr int V = COUT / 32;
    __shared__ float s_sum[COUT];
    __shared__ float s_sq[COUT];
    int t = threadIdx.x;
    if (t < COUT) { s_sum[t] = 0.f; s_sq[t] = 0.f; }
    __syncthreads();

    int gw   = (blockIdx.x * blockDim.x + t) >> 5;
    int lane = t & 31;
    const float* __restrict__ tmp = g_tmp;
    float acc[V];

    if (gw < N) {
        float sn = g_selfnorm[gw];
        if constexpr (V == 4) {
            float4 tv = *(const float4*)&tmp[(size_t)gw * COUT + lane * 4];
            float4 b4 = *(const float4*)&bias[lane * 4];
            acc[0] = b4.x + sn * tv.x; acc[1] = b4.y + sn * tv.y;
            acc[2] = b4.z + sn * tv.z; acc[3] = b4.w + sn * tv.w;
        } else {
            float2 tv = *(const float2*)&tmp[(size_t)gw * COUT + lane * 2];
            float2 b2 = *(const float2*)&bias[lane * 2];
            acc[0] = b2.x + sn * tv.x; acc[1] = b2.y + sn * tv.y;
        }
        int r0 = g_rowstart[gw], r1 = g_rowstart[gw + 1];
        for (int e = r0; e < r1; e++) {
            int   s  = g_csr_src[e];
            float nm = g_csr_nm[e];
            if constexpr (V == 4) {
                float4 v = *(const float4*)&tmp[(size_t)s * COUT + lane * 4];
                acc[0] = fmaf(nm, v.x, acc[0]); acc[1] = fmaf(nm, v.y, acc[1]);
                acc[2] = fmaf(nm, v.z, acc[2]); acc[3] = fmaf(nm, v.w, acc[3]);
            } else {
                float2 v = *(const float2*)&tmp[(size_t)s * COUT + lane * 2];
                acc[0] = fmaf(nm, v.x, acc[0]); acc[1] = fmaf(nm, v.y, acc[1]);
            }
        }
        if constexpr (V == 4) {
            *(float4*)&g_agg[(size_t)gw * COUT + lane * 4] = make_float4(acc[0], acc[1], acc[2], acc[3]);
        } else {
            *(float2*)&g_agg[(size_t)gw * COUT + lane * 2] = make_float2(acc[0], acc[1]);
        }
        #pragma unroll
        for (int j = 0; j < V; j++) {
            atomicAdd(&s_sum[lane * V + j], acc[j]);
            atomicAdd(&s_sq[lane * V + j], acc[j] * acc[j]);
        }
    }
    __syncthreads();
    if (t < COUT) {
        atomicAdd(&g_bnsum[t], s_sum[t]);
        atomicAdd(&g_bnsq[t],  s_sq[t]);
    }
}

// ---------------- BN params: scale/shift from sums, re-zero sums ----------------
template<int COUT>
__global__ void k_bnparam(const float* __restrict__ gam, const float* __restrict__ bet,
                          float invN) {
    int c = threadIdx.x;
    float m = g_bnsum[c] * invN;
    float v = g_bnsq[c] * invN - m * m;
    float inv = rsqrtf(v + 1e-5f);
    float sc = gam[c] * inv;
    g_scale[c] = sc;
    g_shift[c] = bet[c] - m * sc;
    g_bnsum[c] = 0.f;
    g_bnsq[c]  = 0.f;
}

// ---------------- final BN+ReLU writing d_out ----------------
__global__ void k_bnfinal(float* __restrict__ out, int total) {
    int idx = blockIdx.x * blockDim.x + threadIdx.x;
    if (idx >= total) return;
    int c = idx & (LOUT - 1);
    out[idx] = fmaxf(fmaf(g_agg[idx], g_scale[c], g_shift[c]), 0.f);
}

// ---------------- launch ----------------
extern "C" void kernel_launch(void* const* d_in, const int* in_sizes, int n_in,
                              void* d_out, int out_size) {
    const float* x   = (const float*)d_in[0];
    const void*  ei  = d_in[1];
    const float* ew  = (const float*)d_in[2];
    const float* W0  = (const float*)d_in[3];
    const float* b0  = (const float*)d_in[4];
    const float* ga0 = (const float*)d_in[5];
    const float* be0 = (const float*)d_in[6];
    const float* W1  = (const float*)d_in[7];
    const float* b1  = (const float*)d_in[8];
    const float* ga1 = (const float*)d_in[9];
    const float* be1 = (const float*)d_in[10];
    const float* Wf  = (const float*)d_in[11];
    const float* bf  = (const float*)d_in[12];
    const float* gaf = (const float*)d_in[13];
    const float* bef = (const float*)d_in[14];

    int N = in_sizes[0] / CH;
    int E = in_sizes[2];
    float invN = 1.0f / (float)N;

    // device address of g_agg (NEVER pass a __device__ symbol directly from host)
    float* agg_ptr = nullptr;
    cudaGetSymbolAddress((void**)&agg_ptr, g_agg);

    int nb_n = (N + 255) / 256;
    int nb_e = (E + 255) / 256;
    int gemm_blocks = (N + 127) / 128;
    int agg_blocks  = (N * 32 + 511) / 512;

    // preprocessing (gemm0 interleaved: it has no preprocessing deps)
    k_init<<<nb_n, 256>>>(ei, N);
    k_deg<<<nb_e, 256>>>(ei, ew, E);
    k_scan_dis<<<1, 1024>>>(N);
    k_gemm<CH, false><<<gemm_blocks, 256>>>(x, W0, N);   // profiled slot
    k_fill<<<nb_e, 256>>>(ei, ew, E);

    // layer 0
    k_agg<CH><<<agg_blocks, 512>>>(b0, N);
    k_bnparam<CH><<<1, CH>>>(ga0, be0, invN);
    // layer 1 (BN+ReLU fused into A-load)
    k_gemm<CH, true><<<gemm_blocks, 256>>>(agg_ptr, W1, N);
    k_agg<CH><<<agg_blocks, 512>>>(b1, N);
    k_bnparam<CH><<<1, CH>>>(ga1, be1, invN);
    // layer 2
    k_gemm<LOUT, true><<<gemm_blocks, 256>>>(agg_ptr, Wf, N);
    k_agg<LOUT><<<agg_blocks, 512>>>(bf, N);
    k_bnparam<LOUT><<<1, LOUT>>>(gaf, bef, invN);
    k_bnfinal<<<(N * LOUT + 255) / 256, 256>>>((float*)d_out, N * LOUT);
}